// round 9
// baseline (speedup 1.0000x reference)
#include <cuda_runtime.h>
#include <math.h>

#define Nn 1024
#define Ee 4096
#define NB 64
#define NKB 16   // Nn / NB
#define GPB 136  // persistent grid blocks (1 per SM, all co-resident)

// ---------------- scratch (static device globals; no allocation) ----------------
__device__ int   d_heads[Ee], d_tails[Ee];
__device__ float d_s[Ee], d_sigma[Ee];
__device__ float d_u[4][Nn];
__device__ float d_r[Nn], d_z[Nn], d_v1[Nn], d_v2[Nn];
__device__ float d_L [Nn * Nn];
__device__ float d_L2[Nn * Nn];        // L^2; reused as Lfac (factor panels) inside chol
__device__ float d_S [Nn * Nn];
__device__ float d_U [Nn * Nn];        // transposed factor panels (backward solve)
__device__ float d_Ht[(size_t)Ee * Nn];
__device__ float d_Linv[NKB * NB * NB];
__device__ unsigned g_gen_dev[4];
__device__ unsigned g_cnt_dev[4];
// dataflow flags for the Cholesky DAG
__device__ int f_q;                    // Linv(k) ready when f_q >= k+1
__device__ int f_res;                  // residual r ready
__device__ int f_z;                    // z ready
__device__ int f_p[16];                // panel row rb stored for step k when f_p[rb] >= k+1
__device__ int f_t[256];               // tile (I,J): number of completed syrk updates

#define d_Lfac d_L2

__device__ __forceinline__ void spin_ge(const int* f, int target) {
    while (*(volatile const int*)f < target) { }
}
__device__ __forceinline__ void setflag(int* f, int v) {
    __syncthreads();
    __threadfence();
    if (threadIdx.x == 0) *(volatile int*)f = v;
}

// ================= grid barrier (spin) =================
__device__ __forceinline__ void gridbar(int which, unsigned target, unsigned count) {
    __syncthreads();
    if (threadIdx.x == 0) {
        __threadfence();
        unsigned v = atomicAdd(&g_cnt_dev[which], 1u);
        if (v == count - 1) {
            atomicExch(&g_cnt_dev[which], 0u);
            __threadfence();
            atomicExch(&g_gen_dev[which], target);
        } else {
            while (*(volatile unsigned*)&g_gen_dev[which] < target) { }
        }
        __threadfence();
    }
    __syncthreads();
}

// ---------------- persistent front: extract + init + assemble + 3 matvecs ----------------
__global__ void __launch_bounds__(256, 1)
k_front(const float* __restrict__ B, const float* __restrict__ F,
        const float* __restrict__ Cu, const float* __restrict__ Cx,
        const float* __restrict__ s0, const float* __restrict__ q) {
    int bid = blockIdx.x, t = threadIdx.x;
    __shared__ float ws[8];
    unsigned gen = 0;
    if (bid == 0 && t == 0) { g_gen_dev[2] = 0u; g_cnt_dev[2] = 0u; }
    for (int idx = bid * 256 + t; idx < Nn * Ee; idx += GPB * 256) {
        float v = B[idx];
        int e = idx & (Ee - 1), n = idx >> 12;
        if (v > 0.5f)       d_heads[e] = n;
        else if (v < -0.5f) d_tails[e] = n;
        if (idx < Nn * Nn) d_L[idx] = 0.f;
        if (idx < Ee) {
            size_t d = (size_t)idx * Ee + idx;
            float f = F[d];
            d_s[idx] = f * s0[idx];
            d_sigma[idx] = f * f * Cx[d] + Cu[d];
        }
        if (idx < Nn) d_u[0][idx] = q[idx];
    }
    gridbar(0, ++gen, GPB);
    for (int e = bid * 256 + t; e < Ee; e += GPB * 256) {
        float se = d_s[e];
        int h = d_heads[e], tl = d_tails[e];
        atomicAdd(&d_L[h * Nn + h],  se);
        atomicAdd(&d_L[tl * Nn + tl],  se);
        atomicAdd(&d_L[h * Nn + tl], -se);
        atomicAdd(&d_L[tl * Nn + h], -se);
    }
    gridbar(0, ++gen, GPB);
    for (int m = 0; m < 3; m++) {
        for (int row = bid; row < Nn; row += GPB) {
            float4 lv = *(const float4*)&d_L[(size_t)row * Nn + t * 4];
            float4 uv = *(const float4*)&d_u[m][t * 4];
            float acc = lv.x * uv.x + lv.y * uv.y + lv.z * uv.z + lv.w * uv.w;
            for (int off = 16; off; off >>= 1) acc += __shfl_down_sync(0xffffffffu, acc, off);
            if ((t & 31) == 0) ws[t >> 5] = acc;
            __syncthreads();
            if (t == 0) {
                float s = 0.f;
#pragma unroll
                for (int w = 0; w < 8; w++) s += ws[w];
                d_u[m + 1][row] = s;
            }
            __syncthreads();
        }
        gridbar(0, ++gen, GPB);
    }
}

// ---------------- L2 = L * L^T (symmetric; compute lower, mirror; prefetched) ----------------
__global__ void k_gemmL2() {
    if (blockIdx.x == 0 && blockIdx.y == 0 && threadIdx.x == 0) {
        g_gen_dev[1] = 0u; g_cnt_dev[1] = 0u;
    }
    if (blockIdx.y < blockIdx.x) return;
    __shared__ float As[16][65], Bs[16][65];
    __shared__ float Ts[64][65];
    int I = blockIdx.y * 64, J = blockIdx.x * 64;
    int t = threadIdx.x;
    int lm = t >> 2, lk = (t & 3) << 2;
    int ty = t >> 4, tx = t & 15;
    float acc[4][4] = {};
    float4 av = *(const float4*)&d_L[(size_t)(I + lm) * Nn + lk];
    float4 bv = *(const float4*)&d_L[(size_t)(J + lm) * Nn + lk];
    As[lk + 0][lm] = av.x; As[lk + 1][lm] = av.y; As[lk + 2][lm] = av.z; As[lk + 3][lm] = av.w;
    Bs[lk + 0][lm] = bv.x; Bs[lk + 1][lm] = bv.y; Bs[lk + 2][lm] = bv.z; Bs[lk + 3][lm] = bv.w;
    for (int k0 = 0; k0 < Nn; k0 += 16) {
        __syncthreads();
        bool has = (k0 + 16 < Nn);
        float4 an, bn;
        if (has) {
            an = *(const float4*)&d_L[(size_t)(I + lm) * Nn + k0 + 16 + lk];
            bn = *(const float4*)&d_L[(size_t)(J + lm) * Nn + k0 + 16 + lk];
        }
#pragma unroll
        for (int kk = 0; kk < 16; kk++) {
            float ar[4], br[4];
#pragma unroll
            for (int i = 0; i < 4; i++) { ar[i] = As[kk][ty * 4 + i]; br[i] = Bs[kk][tx * 4 + i]; }
#pragma unroll
            for (int i = 0; i < 4; i++)
#pragma unroll
                for (int j = 0; j < 4; j++) acc[i][j] += ar[i] * br[j];
        }
        __syncthreads();
        if (has) {
            As[lk + 0][lm] = an.x; As[lk + 1][lm] = an.y; As[lk + 2][lm] = an.z; As[lk + 3][lm] = an.w;
            Bs[lk + 0][lm] = bn.x; Bs[lk + 1][lm] = bn.y; Bs[lk + 2][lm] = bn.z; Bs[lk + 3][lm] = bn.w;
        }
    }
#pragma unroll
    for (int i = 0; i < 4; i++)
#pragma unroll
        for (int j = 0; j < 4; j++)
            d_L2[(size_t)(I + ty * 4 + i) * Nn + J + tx * 4 + j] = acc[i][j];
    if (blockIdx.y != blockIdx.x) {
#pragma unroll
        for (int i = 0; i < 4; i++)
#pragma unroll
            for (int j = 0; j < 4; j++)
                Ts[tx * 4 + j][ty * 4 + i] = acc[i][j];
        __syncthreads();
        for (int idx = t; idx < 64 * 64; idx += 256) {
            int r = idx >> 6, c = idx & 63;
            d_L2[(size_t)(J + r) * Nn + I + c] = Ts[r][c];
        }
    }
}

// ---------------- fused buildHt + gemmS (persistent, GPB blocks) ----------------
__device__ void gemmS_tile(int I, int J, const float* __restrict__ Cw) {
    __shared__ float As[16][64], Bs[16][64];
    int t = threadIdx.x;
    int ldk = t >> 4, ldm = (t & 15) << 2;
    int ty = t >> 4, tx = t & 15;
    float acc[4][4] = {};
    __syncthreads();
    {
        float sg = d_sigma[ldk];
        const float* row = &d_Ht[(size_t)ldk * Nn];
        float4 av = *(const float4*)&row[I + ldm];
        float4 bv = *(const float4*)&row[J + ldm];
        av.x *= sg; av.y *= sg; av.z *= sg; av.w *= sg;
        *(float4*)&As[ldk][ldm] = av;
        *(float4*)&Bs[ldk][ldm] = bv;
    }
    for (int e0 = 0; e0 < Ee; e0 += 16) {
        __syncthreads();
        bool has = (e0 + 16 < Ee);
        float4 an, bn; float sgn = 0.f;
        if (has) {
            sgn = d_sigma[e0 + 16 + ldk];
            const float* row = &d_Ht[(size_t)(e0 + 16 + ldk) * Nn];
            an = *(const float4*)&row[I + ldm];
            bn = *(const float4*)&row[J + ldm];
        }
        // kk-lookahead: LDS for kk+1 issued before kk's FMAs consume kk's regs
        float4 a4 = *(const float4*)&As[0][ty * 4];
        float4 b4 = *(const float4*)&Bs[0][tx * 4];
#pragma unroll
        for (int kk = 0; kk < 16; kk++) {
            float4 a4n, b4n;
            if (kk < 15) {
                a4n = *(const float4*)&As[kk + 1][ty * 4];
                b4n = *(const float4*)&Bs[kk + 1][tx * 4];
            }
            float ar[4] = {a4.x, a4.y, a4.z, a4.w};
            float br[4] = {b4.x, b4.y, b4.z, b4.w};
#pragma unroll
            for (int i = 0; i < 4; i++)
#pragma unroll
                for (int j = 0; j < 4; j++) acc[i][j] += ar[i] * br[j];
            if (kk < 15) { a4 = a4n; b4 = b4n; }
        }
        __syncthreads();
        if (has) {
            an.x *= sgn; an.y *= sgn; an.z *= sgn; an.w *= sgn;
            *(float4*)&As[ldk][ldm] = an;
            *(float4*)&Bs[ldk][ldm] = bn;
        }
    }
#pragma unroll
    for (int i = 0; i < 4; i++)
#pragma unroll
        for (int j = 0; j < 4; j++) {
            size_t idx = (size_t)(I + ty * 4 + i) * Nn + J + tx * 4 + j;
            d_S[idx] = acc[i][j] + Cw[idx];
        }
    __syncthreads();
}

__global__ void __launch_bounds__(256, 1)
k_HtS(const float* __restrict__ a, const float* __restrict__ Cw) {
    int bid = blockIdx.x, t = threadIdx.x;
    if (bid == 0) {
        if (t < 256) f_t[t] = 0;
        if (t < 16)  f_p[t] = 0;
        if (t == 0)  { f_q = 0; f_res = 0; f_z = 0; }
    }
    float a1 = a[1], a2 = a[2], a3 = a[3];
    for (int e = bid; e < Ee; e += GPB) {
        int h = d_heads[e], tt = d_tails[e];
        float V0 = d_u[0][h] - d_u[0][tt];
        float V1 = d_u[1][h] - d_u[1][tt];
        float V2 = d_u[2][h] - d_u[2][tt];
        float w0 = a1 * V0 + a2 * V1 + a3 * V2;
        float w1 = a2 * V0 + a3 * V1;
        float w2 = a3 * V0;
        float4 lh = *(const float4*)&d_L [(size_t)h  * Nn + t * 4];
        float4 lt = *(const float4*)&d_L [(size_t)tt * Nn + t * 4];
        float4 qh = *(const float4*)&d_L2[(size_t)h  * Nn + t * 4];
        float4 qt = *(const float4*)&d_L2[(size_t)tt * Nn + t * 4];
        float4 v;
        v.x = w1 * (lh.x - lt.x) + w2 * (qh.x - qt.x);
        v.y = w1 * (lh.y - lt.y) + w2 * (qh.y - qt.y);
        v.z = w1 * (lh.z - lt.z) + w2 * (qh.z - qt.z);
        v.w = w1 * (lh.w - lt.w) + w2 * (qh.w - qt.w);
        int n0 = t * 4;
        float* vp = (float*)&v;
        if (h  >= n0 && h  < n0 + 4) vp[h  - n0] += w0;
        if (tt >= n0 && tt < n0 + 4) vp[tt - n0] -= w0;
        *(float4*)&d_Ht[(size_t)e * Nn + n0] = v;
    }
    gridbar(2, 1, GPB);
    for (int item = bid; item < 136; item += GPB) {
        int bi = (int)((sqrtf(8.f * item + 1.f) - 1.f) * 0.5f);
        while ((bi + 1) * (bi + 2) / 2 <= item) bi++;
        while (bi * (bi + 1) / 2 > item) bi--;
        int bj = item - bi * (bi + 1) / 2;
        gemmS_tile(bi * 64, bj * 64, Cw);
    }
}

// ================= persistent Cholesky (dataflow) + solve + output =================

// warp-synchronous 32x32 Cholesky on Am[off..off+31][off..off+31] (warp 0; stride 65)
__device__ __forceinline__ void chol32s(float* Am, int off) {
    int t = threadIdx.x;
    if (t < 32) {
        for (int k = 0; k < 32; k++) {
            float dk = Am[(off + k) * 65 + off + k];
            float rs = rsqrtf(dk);
            if (t == k)      Am[(off + k) * 65 + off + k] = dk * rs;
            else if (t > k)  Am[(off + t) * 65 + off + k] *= rs;
            __syncwarp();
            if (t > k) {
                float ltk = Am[(off + t) * 65 + off + k];
                for (int c = k + 1; c <= t; c++)
                    Am[(off + t) * 65 + off + c] -= ltk * Am[(off + c) * 65 + off + k];
            }
            __syncwarp();
        }
    }
}

// lane-per-column 32x32 lower-triangular inverse; column-local, sync-free
__device__ __forceinline__ void inv32s(const float* Am, float* Bm, int off) {
    int t = threadIdx.x;
    if (t < 32) {
        int c = off + t;
        for (int r = 0; r < 64; r++) Bm[r * 65 + c] = (r == c) ? 1.f : 0.f;
        for (int k = 0; k < 32; k++) {
            float inva = 1.f / Am[(off + k) * 65 + off + k];
            float bk = Bm[(off + k) * 65 + c] * inva;
            Bm[(off + k) * 65 + c] = bk;
            for (int r = k + 1; r < 32; r++)
                Bm[(off + r) * 65 + c] -= Am[(off + r) * 65 + off + k] * bk;
        }
    }
}

// hierarchical 64x64 potrf + full triangular inverse. Am: raw tile (destroyed).
// Linv written to Bm (stride 65) AND d_Linv[kblk] (row-major 64x64).
__device__ void potrf64(int kblk, float* Am, float* Bm, float* Tm) {
    int t = threadIdx.x;
    int gr = t >> 3, gc = (t & 7) << 2;
    __syncthreads();
    chol32s(Am, 0);
    __syncthreads();
    inv32s(Am, Bm, 0);
    __syncthreads();
    {   // L21 = A21 * I11^T -> Tm
        float acc[4] = {0.f, 0.f, 0.f, 0.f};
        for (int m = 0; m < 32; m++) {
            float av = Am[(32 + gr) * 65 + m];
#pragma unroll
            for (int j = 0; j < 4; j++) acc[j] += av * Bm[(gc + j) * 65 + m];
        }
#pragma unroll
        for (int j = 0; j < 4; j++) Tm[gr * 33 + gc + j] = acc[j];
    }
    __syncthreads();
    {   // A22 -= L21 L21^T
        float acc[4] = {0.f, 0.f, 0.f, 0.f};
        for (int m = 0; m < 32; m++) {
            float av = Tm[gr * 33 + m];
#pragma unroll
            for (int j = 0; j < 4; j++) acc[j] += av * Tm[(gc + j) * 33 + m];
        }
#pragma unroll
        for (int j = 0; j < 4; j++) Am[(32 + gr) * 65 + 32 + gc + j] -= acc[j];
    }
    __syncthreads();
    chol32s(Am, 32);
    __syncthreads();
    inv32s(Am, Bm, 32);
    __syncthreads();
    {   // T2 = L21 * I11 (in place in Tm)
        float acc[4] = {0.f, 0.f, 0.f, 0.f};
        for (int m = 0; m < 32; m++) {
            float av = Tm[gr * 33 + m];
#pragma unroll
            for (int j = 0; j < 4; j++) acc[j] += av * Bm[m * 65 + gc + j];
        }
        __syncthreads();
#pragma unroll
        for (int j = 0; j < 4; j++) Tm[gr * 33 + gc + j] = acc[j];
    }
    __syncthreads();
    {   // I21 = -I22 * T2
        float acc[4] = {0.f, 0.f, 0.f, 0.f};
        for (int m = 0; m < 32; m++) {
            float av = Bm[(32 + gr) * 65 + 32 + m];
#pragma unroll
            for (int j = 0; j < 4; j++) acc[j] += av * Tm[m * 33 + gc + j];
        }
#pragma unroll
        for (int j = 0; j < 4; j++) Bm[(32 + gr) * 65 + gc + j] = -acc[j];
    }
    __syncthreads();
    for (int idx = t; idx < NB * NB; idx += 256) {
        int r = idx >> 6, c = idx & 63;
        d_Linv[kblk * NB * NB + idx] = Bm[r * 65 + c];
    }
    __syncthreads();
}

// worker trsm: input from d_S (pristine); writes d_Lfac + d_U (unchanged from R8)
__device__ void trsm_dev(int kblk, int panel, float (*At)[NB + 1], float (*Lv)[NB + 1]) {
    int o = kblk * NB, t = threadIdx.x;
    int r0 = o + NB + panel * NB;
    __syncthreads();
    for (int idx = t; idx < NB * NB; idx += 256) {
        int r = idx >> 6, c = idx & 63;
        At[r][c] = d_S[(size_t)(r0 + r) * Nn + o + c];
        Lv[r][c] = d_Linv[kblk * NB * NB + idx];
    }
    __syncthreads();
    int ty = t >> 4, tx = t & 15;
    float acc[4][4] = {};
    for (int m = 0; m < NB; m++) {
        float ar[4], br[4];
#pragma unroll
        for (int i = 0; i < 4; i++) { ar[i] = At[ty * 4 + i][m]; br[i] = Lv[tx * 4 + i][m]; }
#pragma unroll
        for (int i = 0; i < 4; i++)
#pragma unroll
            for (int j = 0; j < 4; j++) acc[i][j] += ar[i] * br[j];
    }
    __syncthreads();
#pragma unroll
    for (int i = 0; i < 4; i++)
#pragma unroll
        for (int j = 0; j < 4; j++) {
            At[ty * 4 + i][tx * 4 + j] = acc[i][j];
            Lv[tx * 4 + j][ty * 4 + i] = acc[i][j];
        }
    __syncthreads();
    for (int idx = t; idx < NB * NB; idx += 256) {
        int r = idx >> 6, c = idx & 63;
        d_Lfac[(size_t)(r0 + r) * Nn + o + c] = At[r][c];
        d_U[(size_t)(o + r) * Nn + r0 + c]   = Lv[r][c];
    }
    __syncthreads();
}

// trailing update: d_S(tile) -= P_bi P_bj^T, panels read from d_Lfac
__device__ void syrk_dev(int kblk, int bi, int bj, float (*Pi)[NB + 1], float (*Pj)[NB + 1]) {
    int o = kblk * NB, t = threadIdx.x;
    int ri = o + NB + bi * NB, rj = o + NB + bj * NB;
    __syncthreads();
    for (int idx = t; idx < NB * NB; idx += 256) {
        int r = idx >> 6, c = idx & 63;
        Pi[r][c] = d_Lfac[(size_t)(ri + r) * Nn + o + c];
        Pj[r][c] = d_Lfac[(size_t)(rj + r) * Nn + o + c];
    }
    __syncthreads();
    int ty = t >> 4, tx = t & 15;
    float acc[4][4] = {};
    for (int m = 0; m < NB; m++) {
        float ar[4], br[4];
#pragma unroll
        for (int i = 0; i < 4; i++) { ar[i] = Pi[ty * 4 + i][m]; br[i] = Pj[tx * 4 + i][m]; }
#pragma unroll
        for (int i = 0; i < 4; i++)
#pragma unroll
            for (int j = 0; j < 4; j++) acc[i][j] += ar[i] * br[j];
    }
    __syncthreads();
#pragma unroll
    for (int i = 0; i < 4; i++)
#pragma unroll
        for (int j = 0; j < 4; j++) {
            size_t idx = (size_t)(ri + ty * 4 + i) * Nn + rj + tx * 4 + j;
            d_S[idx] -= acc[i][j];
        }
    __syncthreads();
}

// forward + backward triangular solves by ONE block (256 threads)
__device__ void solve_dev(float* sh, float (*shB)[NB + 1]) {
    int t = threadIdx.x;
    int r = t >> 2, q = t & 3;
    float* yv   = sh;
    float* zz   = sh + 1024;
    float* part = sh + 2048;
    float* tvv  = sh + 2112;
    for (int k = 0; k < NKB; k++) {
        int o = k * NB;
        float acc = 0.f;
        const float* Srow = &d_Lfac[(size_t)(o + r) * Nn + q * 16];
        for (int cb = 0; cb < k; cb++) {
#pragma unroll
            for (int m = 0; m < 4; m++) {
                float4 v = *(const float4*)&Srow[cb * 64 + m * 4];
                int j = cb * 64 + q * 16 + m * 4;
                acc += v.x * yv[j] + v.y * yv[j + 1] + v.z * yv[j + 2] + v.w * yv[j + 3];
            }
        }
        acc += __shfl_xor_sync(0xffffffffu, acc, 1);
        acc += __shfl_xor_sync(0xffffffffu, acc, 2);
        if (q == 0) part[r] = acc;
        for (int idx = t; idx < NB * NB; idx += 256)
            shB[idx >> 6][idx & 63] = d_Linv[k * NB * NB + idx];
        __syncthreads();
        if (t < NB) tvv[t] = d_r[o + t] - part[t];
        __syncthreads();
        if (t < NB) {
            float a2 = 0.f;
#pragma unroll
            for (int m = 0; m < NB; m++) a2 += shB[t][m] * tvv[m];
            yv[o + t] = a2;
        }
        __syncthreads();
    }
    for (int k = NKB - 1; k >= 0; k--) {
        int o = k * NB;
        float acc = 0.f;
        const float* Urow = &d_U[(size_t)(o + r) * Nn + q * 16];
        for (int rb = k + 1; rb < NKB; rb++) {
#pragma unroll
            for (int m = 0; m < 4; m++) {
                float4 v = *(const float4*)&Urow[rb * 64 + m * 4];
                int j = rb * 64 + q * 16 + m * 4;
                acc += v.x * zz[j] + v.y * zz[j + 1] + v.z * zz[j + 2] + v.w * zz[j + 3];
            }
        }
        acc += __shfl_xor_sync(0xffffffffu, acc, 1);
        acc += __shfl_xor_sync(0xffffffffu, acc, 2);
        if (q == 0) part[r] = acc;
        for (int idx = t; idx < NB * NB; idx += 256)
            shB[idx >> 6][idx & 63] = d_Linv[k * NB * NB + idx];
        __syncthreads();
        if (t < NB) tvv[t] = yv[o + t] - part[t];
        __syncthreads();
        if (t < NB) {
            float a2 = 0.f;
#pragma unroll
            for (int m = 0; m < NB; m++) a2 += shB[m][t] * tvv[m];
            zz[o + t] = a2;
        }
        __syncthreads();
    }
    for (int n = t; n < Nn; n += 256) d_z[n] = zz[n];
    __syncthreads();
}

__device__ void matvec_dev(const float* src, float* dst, int bid, int t, float* ws) {
    for (int row = bid; row < Nn; row += GPB) {
        float4 lv = *(const float4*)&d_L[(size_t)row * Nn + t * 4];
        float4 zv = *(const float4*)&src[t * 4];
        float acc = lv.x * zv.x + lv.y * zv.y + lv.z * zv.z + lv.w * zv.w;
        for (int off = 16; off; off >>= 1) acc += __shfl_down_sync(0xffffffffu, acc, off);
        if ((t & 31) == 0) ws[t >> 5] = acc;
        __syncthreads();
        if (t == 0) {
            float s = 0.f;
#pragma unroll
            for (int w = 0; w < 8; w++) s += ws[w];
            dst[row] = s;
        }
        __syncthreads();
    }
}

__global__ void __launch_bounds__(256, 1)
k_chol_all(const float* __restrict__ a, const float* __restrict__ y, float* __restrict__ out) {
    __shared__ float shAf[64 * 65];
    __shared__ float shBf[64 * 65];
    __shared__ float shT[32 * 33];
    __shared__ float ws[8];
    int bid = blockIdx.x, t = threadIdx.x;
    int ty = t >> 4, tx = t & 15;

    if (bid == 0) {
        // potrf(0): load raw tile, hierarchical factor+inverse; Linv(0) -> pInv smem
        float* pInv = shBf;
        float* pOth = shAf;
        __syncthreads();
        for (int idx = t; idx < NB * NB; idx += 256) {
            int r = idx >> 6, c = idx & 63;
            pOth[r * 65 + c] = d_S[(size_t)r * Nn + c];
        }
        potrf64(0, pOth, pInv, shT);
        setflag(&f_q, 1);

        for (int k = 0; k < NKB - 1; k++) {
            // ---- trsm panel0 (Lv already resident in pInv) ----
            if (t == 0) { spin_ge(&f_t[(k + 1) * 16 + k], k); __threadfence(); }
            __syncthreads();
            int o = k * NB, r0 = o + NB;
            for (int idx = t; idx < NB * NB; idx += 256) {
                int r = idx >> 6, c = idx & 63;
                pOth[r * 65 + c] = d_S[(size_t)(r0 + r) * Nn + o + c];
            }
            __syncthreads();
            {
                float acc[4][4] = {};
                for (int m = 0; m < NB; m++) {
                    float ar[4], br[4];
#pragma unroll
                    for (int i = 0; i < 4; i++) {
                        ar[i] = pOth[(ty * 4 + i) * 65 + m];
                        br[i] = pInv[(tx * 4 + i) * 65 + m];
                    }
#pragma unroll
                    for (int i = 0; i < 4; i++)
#pragma unroll
                        for (int j = 0; j < 4; j++) acc[i][j] += ar[i] * br[j];
                }
                __syncthreads();
#pragma unroll
                for (int i = 0; i < 4; i++)
#pragma unroll
                    for (int j = 0; j < 4; j++)
                        pOth[(ty * 4 + i) * 65 + tx * 4 + j] = acc[i][j];
            }
            // ---- syrk(0,0): raw next diag -> pInv (Linv(k) dead now) ----
            if (t == 0) { spin_ge(&f_t[(k + 1) * 16 + (k + 1)], k); __threadfence(); }
            __syncthreads();
            {
                float acc[4][4] = {};
                for (int m = 0; m < NB; m++) {
                    float ar[4], br[4];
#pragma unroll
                    for (int i = 0; i < 4; i++) {
                        ar[i] = pOth[(ty * 4 + i) * 65 + m];
                        br[i] = pOth[(tx * 4 + i) * 65 + m];
                    }
#pragma unroll
                    for (int i = 0; i < 4; i++)
#pragma unroll
                        for (int j = 0; j < 4; j++) acc[i][j] += ar[i] * br[j];
                }
                __syncthreads();
                int o2 = (k + 1) * NB;
#pragma unroll
                for (int i = 0; i < 4; i++)
#pragma unroll
                    for (int j = 0; j < 4; j++)
                        pInv[(ty * 4 + i) * 65 + tx * 4 + j] =
                            d_S[(size_t)(o2 + ty * 4 + i) * Nn + o2 + tx * 4 + j] - acc[i][j];
            }
            // ---- potrf(k+1): raw in pInv, Linv(k+1) -> pOth; swap ----
            potrf64(k + 1, pInv, pOth, shT);
            float* tmp = pInv; pInv = pOth; pOth = tmp;
            setflag(&f_q, k + 2);
        }
    } else {
        if (bid == GPB - 1) {
            if (t == 0) { g_gen_dev[0] = 0u; g_cnt_dev[0] = 0u; }   // reset front barrier
            float a0 = a[0], a1 = a[1], a2 = a[2], a3 = a[3];
            for (int n = t; n < Nn; n += 256)
                d_r[n] = y[n] - (a0 * d_u[0][n] + a1 * d_u[1][n] + a2 * d_u[2][n] + a3 * d_u[3][n]);
            setflag(&f_res, 1);
        }
        float (*A2)[NB + 1] = (float (*)[NB + 1])shAf;
        float (*B2)[NB + 1] = (float (*)[NB + 1])shBf;
        for (int k = 0; k < NKB - 1; k++) {
            int rb = NKB - 1 - k;
            if (bid <= rb) {
                int I = k + bid;
                if (t == 0) {
                    spin_ge(&f_q, k + 1);
                    spin_ge(&f_t[I * 16 + k], k);
                    __threadfence();
                }
                __syncthreads();
                trsm_dev(k, bid - 1, A2, B2);
                setflag(&f_p[I], k + 1);
            }
            int T = rb * (rb + 1) / 2;
            for (int tt = bid; tt < T; tt += GPB - 1) {
                int bi = (int)((sqrtf(8.f * tt + 1.f) - 1.f) * 0.5f);
                while ((bi + 1) * (bi + 2) / 2 <= tt) bi++;
                while (bi * (bi + 1) / 2 > tt) bi--;
                int bj = tt - bi * (bi + 1) / 2;
                int I = k + 1 + bi, J = k + 1 + bj;
                if (t == 0) {
                    spin_ge(&f_p[I], k + 1);
                    spin_ge(&f_p[J], k + 1);
                    spin_ge(&f_t[I * 16 + J], k);
                    __threadfence();
                }
                __syncthreads();
                syrk_dev(k, bi, bj, A2, B2);
                setflag(&f_t[I * 16 + J], k + 1);
            }
        }
    }

    if (bid == 0) {
        if (t == 0) {
            for (int rb2 = 1; rb2 < NKB; rb2++) spin_ge(&f_p[rb2], rb2);
            spin_ge(&f_res, 1);
            __threadfence();
        }
        __syncthreads();
        solve_dev(shAf, (float (*)[NB + 1])shBf);
        setflag(&f_z, 1);
    }
    if (t == 0) { spin_ge(&f_z, 1); __threadfence(); }
    __syncthreads();

    matvec_dev(d_z,  d_v1, bid, t, ws);
    gridbar(1, 1, GPB);
    matvec_dev(d_v1, d_v2, bid, t, ws);
    gridbar(1, 2, GPB);

    float a1 = a[1], a2 = a[2], a3 = a[3];
    for (int e = bid * 256 + t; e < Ee; e += GPB * 256) {
        int h = d_heads[e], tl = d_tails[e];
        float V0 = d_u[0][h] - d_u[0][tl];
        float V1 = d_u[1][h] - d_u[1][tl];
        float V2 = d_u[2][h] - d_u[2][tl];
        float w0 = a1 * V0 + a2 * V1 + a3 * V2;
        float w1 = a2 * V0 + a3 * V1;
        float w2 = a3 * V0;
        float dotv = w0 * (d_z[h] - d_z[tl]) + w1 * (d_v1[h] - d_v1[tl]) + w2 * (d_v2[h] - d_v2[tl]);
        out[e] = fmaxf(d_s[e] + d_sigma[e] * dotv, 0.f);
    }
}

// ---------------- launch ----------------
extern "C" void kernel_launch(void* const* d_in, const int* in_sizes, int n_in,
                              void* d_out, int out_size) {
    (void)in_sizes; (void)n_in; (void)out_size;
    const float* F  = (const float*)d_in[0];
    const float* B  = (const float*)d_in[1];
    const float* Cu = (const float*)d_in[2];
    const float* Cw = (const float*)d_in[3];
    const float* Cx = (const float*)d_in[4];
    const float* s0 = (const float*)d_in[5];
    const float* a  = (const float*)d_in[6];
    const float* q  = (const float*)d_in[7];
    const float* y  = (const float*)d_in[8];
    float* out = (float*)d_out;

    k_front<<<GPB, 256>>>(B, F, Cu, Cx, s0, q);     // #1
    k_gemmL2<<<dim3(16, 16), 256>>>();              // #2
    k_HtS<<<GPB, 256>>>(a, Cw);                     // #3
    k_chol_all<<<GPB, 256>>>(a, y, out);            // #4
}

// round 12
// speedup vs baseline: 1.7948x; 1.7948x over previous
#include <cuda_runtime.h>
#include <math.h>

#define Nn 1024
#define Ee 4096
#define NB 32
#define NKB 32   // Nn / NB
#define GPB 136  // persistent grid blocks (1 per SM, all co-resident)

// ---------------- scratch (static device globals; no allocation) ----------------
__device__ int   d_heads[Ee], d_tails[Ee];
__device__ float d_s[Ee], d_sigma[Ee];
__device__ float d_u[4][Nn];
__device__ float d_r[Nn], d_z[Nn], d_v1[Nn], d_v2[Nn];
__device__ float d_L [Nn * Nn];
__device__ float d_L2[Nn * Nn];        // L^2; reused as Lfac (factor panels) inside chol
__device__ float d_S [Nn * Nn];
__device__ float d_U [Nn * Nn];        // transposed factor panels (backward solve)
__device__ float d_Ht[(size_t)Ee * Nn];
__device__ float d_Linv[NKB * NB * NB];
__device__ unsigned g_gen_dev[4];
__device__ unsigned g_cnt_dev[4];
// dataflow flags for the Cholesky DAG
__device__ int f_q;                    // Linv(k) ready when f_q >= k+1
__device__ int f_res;                  // residual r ready
__device__ int f_z;                    // z ready
__device__ int f_p[NKB];               // panel row rb stored for step k when f_p[rb] >= k+1
__device__ int f_t[NKB * NKB];         // tile (I,J): number of completed syrk updates

#define d_Lfac d_L2

__device__ __forceinline__ void spin_ge(const int* f, int target) {
    while (*(volatile const int*)f < target) { }
}
__device__ __forceinline__ void setflag(int* f, int v) {
    __syncthreads();
    __threadfence();
    if (threadIdx.x == 0) *(volatile int*)f = v;
}

// ================= grid barrier (spin) =================
__device__ __forceinline__ void gridbar(int which, unsigned target, unsigned count) {
    __syncthreads();
    if (threadIdx.x == 0) {
        __threadfence();
        unsigned v = atomicAdd(&g_cnt_dev[which], 1u);
        if (v == count - 1) {
            atomicExch(&g_cnt_dev[which], 0u);
            __threadfence();
            atomicExch(&g_gen_dev[which], target);
        } else {
            while (*(volatile unsigned*)&g_gen_dev[which] < target) { }
        }
        __threadfence();
    }
    __syncthreads();
}

// ---------------- persistent front: extract + init + assemble + 3 matvecs ----------------
__global__ void __launch_bounds__(256, 1)
k_front(const float* __restrict__ B, const float* __restrict__ F,
        const float* __restrict__ Cu, const float* __restrict__ Cx,
        const float* __restrict__ s0, const float* __restrict__ q) {
    int bid = blockIdx.x, t = threadIdx.x;
    __shared__ float ws[8];
    unsigned gen = 0;
    if (bid == 0 && t == 0) { g_gen_dev[2] = 0u; g_cnt_dev[2] = 0u; }
    for (int idx = bid * 256 + t; idx < Nn * Ee; idx += GPB * 256) {
        float v = B[idx];
        int e = idx & (Ee - 1), n = idx >> 12;
        if (v > 0.5f)       d_heads[e] = n;
        else if (v < -0.5f) d_tails[e] = n;
        if (idx < Nn * Nn) d_L[idx] = 0.f;
        if (idx < Ee) {
            size_t d = (size_t)idx * Ee + idx;
            float f = F[d];
            d_s[idx] = f * s0[idx];
            d_sigma[idx] = f * f * Cx[d] + Cu[d];
        }
        if (idx < Nn) d_u[0][idx] = q[idx];
    }
    gridbar(0, ++gen, GPB);
    for (int e = bid * 256 + t; e < Ee; e += GPB * 256) {
        float se = d_s[e];
        int h = d_heads[e], tl = d_tails[e];
        atomicAdd(&d_L[h * Nn + h],  se);
        atomicAdd(&d_L[tl * Nn + tl],  se);
        atomicAdd(&d_L[h * Nn + tl], -se);
        atomicAdd(&d_L[tl * Nn + h], -se);
    }
    gridbar(0, ++gen, GPB);
    for (int m = 0; m < 3; m++) {
        for (int row = bid; row < Nn; row += GPB) {
            float4 lv = *(const float4*)&d_L[(size_t)row * Nn + t * 4];
            float4 uv = *(const float4*)&d_u[m][t * 4];
            float acc = lv.x * uv.x + lv.y * uv.y + lv.z * uv.z + lv.w * uv.w;
            for (int off = 16; off; off >>= 1) acc += __shfl_down_sync(0xffffffffu, acc, off);
            if ((t & 31) == 0) ws[t >> 5] = acc;
            __syncthreads();
            if (t == 0) {
                float s = 0.f;
#pragma unroll
                for (int w = 0; w < 8; w++) s += ws[w];
                d_u[m + 1][row] = s;
            }
            __syncthreads();
        }
        gridbar(0, ++gen, GPB);
    }
}

// ---------------- L2 = L * L^T (symmetric; compute lower, mirror; prefetched) ----------------
__global__ void k_gemmL2() {
    if (blockIdx.x == 0 && blockIdx.y == 0 && threadIdx.x == 0) {
        g_gen_dev[1] = 0u; g_cnt_dev[1] = 0u;
    }
    if (blockIdx.y < blockIdx.x) return;
    __shared__ float As[16][65], Bs[16][65];
    __shared__ float Ts[64][65];
    int I = blockIdx.y * 64, J = blockIdx.x * 64;
    int t = threadIdx.x;
    int lm = t >> 2, lk = (t & 3) << 2;
    int ty = t >> 4, tx = t & 15;
    float acc[4][4] = {};
    float4 av = *(const float4*)&d_L[(size_t)(I + lm) * Nn + lk];
    float4 bv = *(const float4*)&d_L[(size_t)(J + lm) * Nn + lk];
    As[lk + 0][lm] = av.x; As[lk + 1][lm] = av.y; As[lk + 2][lm] = av.z; As[lk + 3][lm] = av.w;
    Bs[lk + 0][lm] = bv.x; Bs[lk + 1][lm] = bv.y; Bs[lk + 2][lm] = bv.z; Bs[lk + 3][lm] = bv.w;
    for (int k0 = 0; k0 < Nn; k0 += 16) {
        __syncthreads();
        bool has = (k0 + 16 < Nn);
        float4 an, bn;
        if (has) {
            an = *(const float4*)&d_L[(size_t)(I + lm) * Nn + k0 + 16 + lk];
            bn = *(const float4*)&d_L[(size_t)(J + lm) * Nn + k0 + 16 + lk];
        }
#pragma unroll
        for (int kk = 0; kk < 16; kk++) {
            float ar[4], br[4];
#pragma unroll
            for (int i = 0; i < 4; i++) { ar[i] = As[kk][ty * 4 + i]; br[i] = Bs[kk][tx * 4 + i]; }
#pragma unroll
            for (int i = 0; i < 4; i++)
#pragma unroll
                for (int j = 0; j < 4; j++) acc[i][j] += ar[i] * br[j];
        }
        __syncthreads();
        if (has) {
            As[lk + 0][lm] = an.x; As[lk + 1][lm] = an.y; As[lk + 2][lm] = an.z; As[lk + 3][lm] = an.w;
            Bs[lk + 0][lm] = bn.x; Bs[lk + 1][lm] = bn.y; Bs[lk + 2][lm] = bn.z; Bs[lk + 3][lm] = bn.w;
        }
    }
#pragma unroll
    for (int i = 0; i < 4; i++)
#pragma unroll
        for (int j = 0; j < 4; j++)
            d_L2[(size_t)(I + ty * 4 + i) * Nn + J + tx * 4 + j] = acc[i][j];
    if (blockIdx.y != blockIdx.x) {
#pragma unroll
        for (int i = 0; i < 4; i++)
#pragma unroll
            for (int j = 0; j < 4; j++)
                Ts[tx * 4 + j][ty * 4 + i] = acc[i][j];
        __syncthreads();
        for (int idx = t; idx < 64 * 64; idx += 256) {
            int r = idx >> 6, c = idx & 63;
            d_L2[(size_t)(J + r) * Nn + I + c] = Ts[r][c];
        }
    }
}

// ---------------- fused buildHt + gemmS (persistent, GPB blocks) ----------------
__device__ void gemmS_tile(int I, int J, const float* __restrict__ Cw) {
    __shared__ float As[16][64], Bs[16][64];
    int t = threadIdx.x;
    int ldk = t >> 4, ldm = (t & 15) << 2;
    int ty = t >> 4, tx = t & 15;
    float acc[4][4] = {};
    __syncthreads();
    {
        float sg = d_sigma[ldk];
        const float* row = &d_Ht[(size_t)ldk * Nn];
        float4 av = *(const float4*)&row[I + ldm];
        float4 bv = *(const float4*)&row[J + ldm];
        av.x *= sg; av.y *= sg; av.z *= sg; av.w *= sg;
        *(float4*)&As[ldk][ldm] = av;
        *(float4*)&Bs[ldk][ldm] = bv;
    }
    for (int e0 = 0; e0 < Ee; e0 += 16) {
        __syncthreads();
        bool has = (e0 + 16 < Ee);
        float4 an, bn; float sgn = 0.f;
        if (has) {
            sgn = d_sigma[e0 + 16 + ldk];
            const float* row = &d_Ht[(size_t)(e0 + 16 + ldk) * Nn];
            an = *(const float4*)&row[I + ldm];
            bn = *(const float4*)&row[J + ldm];
        }
#pragma unroll
        for (int kk = 0; kk < 16; kk++) {
            float4 a4 = *(const float4*)&As[kk][ty * 4];
            float4 b4 = *(const float4*)&Bs[kk][tx * 4];
            float ar[4] = {a4.x, a4.y, a4.z, a4.w};
            float br[4] = {b4.x, b4.y, b4.z, b4.w};
#pragma unroll
            for (int i = 0; i < 4; i++)
#pragma unroll
                for (int j = 0; j < 4; j++) acc[i][j] += ar[i] * br[j];
        }
        __syncthreads();
        if (has) {
            an.x *= sgn; an.y *= sgn; an.z *= sgn; an.w *= sgn;
            *(float4*)&As[ldk][ldm] = an;
            *(float4*)&Bs[ldk][ldm] = bn;
        }
    }
#pragma unroll
    for (int i = 0; i < 4; i++)
#pragma unroll
        for (int j = 0; j < 4; j++) {
            size_t idx = (size_t)(I + ty * 4 + i) * Nn + J + tx * 4 + j;
            d_S[idx] = acc[i][j] + Cw[idx];
        }
    __syncthreads();
}

__global__ void __launch_bounds__(256, 1)
k_HtS(const float* __restrict__ a, const float* __restrict__ Cw) {
    int bid = blockIdx.x, t = threadIdx.x;
    if (bid == 0) {
        for (int i = t; i < NKB * NKB; i += 256) f_t[i] = 0;
        if (t < NKB) f_p[t] = 0;
        if (t == 0)  { f_q = 0; f_res = 0; f_z = 0; }
    }
    float a1 = a[1], a2 = a[2], a3 = a[3];
    for (int e = bid; e < Ee; e += GPB) {
        int h = d_heads[e], tt = d_tails[e];
        float V0 = d_u[0][h] - d_u[0][tt];
        float V1 = d_u[1][h] - d_u[1][tt];
        float V2 = d_u[2][h] - d_u[2][tt];
        float w0 = a1 * V0 + a2 * V1 + a3 * V2;
        float w1 = a2 * V0 + a3 * V1;
        float w2 = a3 * V0;
        float4 lh = *(const float4*)&d_L [(size_t)h  * Nn + t * 4];
        float4 lt = *(const float4*)&d_L [(size_t)tt * Nn + t * 4];
        float4 qh = *(const float4*)&d_L2[(size_t)h  * Nn + t * 4];
        float4 qt = *(const float4*)&d_L2[(size_t)tt * Nn + t * 4];
        float4 v;
        v.x = w1 * (lh.x - lt.x) + w2 * (qh.x - qt.x);
        v.y = w1 * (lh.y - lt.y) + w2 * (qh.y - qt.y);
        v.z = w1 * (lh.z - lt.z) + w2 * (qh.z - qt.z);
        v.w = w1 * (lh.w - lt.w) + w2 * (qh.w - qt.w);
        int n0 = t * 4;
        float* vp = (float*)&v;
        if (h  >= n0 && h  < n0 + 4) vp[h  - n0] += w0;
        if (tt >= n0 && tt < n0 + 4) vp[tt - n0] -= w0;
        *(float4*)&d_Ht[(size_t)e * Nn + n0] = v;
    }
    gridbar(2, 1, GPB);
    for (int item = bid; item < 136; item += GPB) {
        int bi = (int)((sqrtf(8.f * item + 1.f) - 1.f) * 0.5f);
        while ((bi + 1) * (bi + 2) / 2 <= item) bi++;
        while (bi * (bi + 1) / 2 > item) bi--;
        int bj = item - bi * (bi + 1) / 2;
        gemmS_tile(bi * 64, bj * 64, Cw);
    }
}

// ================= persistent Cholesky (dataflow, NB=32) + solve + output =================

// 32x32 Cholesky + triangular inverse, one sync per pivot (raw-column scheme)
__device__ void potrf_core(int kblk, float (*A)[NB + 1], float (*Bi)[NB + 1]) {
    __shared__ float dv[NB];
    int t = threadIdx.x;
    __syncthreads();
    for (int k = 0; k < NB - 1; k++) {
        float dk = A[k][k];
        float invd = 1.f / dk;
        if (t == 0) dv[k] = dk;
        for (int idx = (k + 1) * NB + t; idx < NB * NB; idx += 256) {
            int r = idx >> 5, c = idx & 31;
            float lrk = A[r][k] * invd;
            if (c <= k)          Bi[r][c] -= lrk * Bi[k][c];
            else if (c <= r)     A[r][c]  -= lrk * A[c][k];
        }
        __syncthreads();
    }
    if (t == 0) dv[NB - 1] = A[NB - 1][NB - 1];
    __syncthreads();
    for (int idx = t; idx < NB * NB; idx += 256) {
        int r = idx >> 5, c = idx & 31;
        float bv = (c <= r) ? Bi[r][c] * rsqrtf(dv[r]) : 0.f;
        d_Linv[kblk * NB * NB + idx] = bv;
    }
    __syncthreads();
}

__device__ void potrf_from_global(int kblk, float (*A)[NB + 1], float (*Bi)[NB + 1]) {
    int o = kblk * NB, t = threadIdx.x;
    __syncthreads();
    for (int idx = t; idx < NB * NB; idx += 256) {
        int r = idx >> 5, c = idx & 31;
        A[r][c] = d_S[(size_t)(o + r) * Nn + o + c];
        Bi[r][c] = (r == c) ? 1.f : 0.f;
    }
    potrf_core(kblk, A, Bi);
}

// worker trsm: P = S_panel * Linv^T; writes d_Lfac + d_U. 2x2 microtile.
__device__ void trsm_dev(int kblk, int panel, float (*At)[NB + 1], float (*Lv)[NB + 1], bool store) {
    int o = kblk * NB, t = threadIdx.x;
    int r0 = o + NB + panel * NB;
    __syncthreads();
    for (int idx = t; idx < NB * NB; idx += 256) {
        int r = idx >> 5, c = idx & 31;
        At[r][c] = d_S[(size_t)(r0 + r) * Nn + o + c];
        Lv[r][c] = d_Linv[kblk * NB * NB + idx];
    }
    __syncthreads();
    int ty = t >> 4, tx = t & 15;
    float acc[2][2] = {};
#pragma unroll 8
    for (int m = 0; m < NB; m++) {
        float ar[2], br[2];
#pragma unroll
        for (int i = 0; i < 2; i++) { ar[i] = At[ty * 2 + i][m]; br[i] = Lv[tx * 2 + i][m]; }
#pragma unroll
        for (int i = 0; i < 2; i++)
#pragma unroll
            for (int j = 0; j < 2; j++) acc[i][j] += ar[i] * br[j];
    }
    __syncthreads();
#pragma unroll
    for (int i = 0; i < 2; i++)
#pragma unroll
        for (int j = 0; j < 2; j++) {
            At[ty * 2 + i][tx * 2 + j] = acc[i][j];
            if (store) Lv[tx * 2 + j][ty * 2 + i] = acc[i][j];
        }
    __syncthreads();
    if (store) {
        for (int idx = t; idx < NB * NB; idx += 256) {
            int r = idx >> 5, c = idx & 31;
            d_Lfac[(size_t)(r0 + r) * Nn + o + c] = At[r][c];
            d_U[(size_t)(o + r) * Nn + r0 + c]   = Lv[r][c];
        }
        __syncthreads();
    }
}

// trailing update: d_S(tile) -= P_bi P_bj^T, panels read from d_Lfac
__device__ void syrk_dev(int kblk, int bi, int bj, float (*Pi)[NB + 1], float (*Pj)[NB + 1]) {
    int o = kblk * NB, t = threadIdx.x;
    int ri = o + NB + bi * NB, rj = o + NB + bj * NB;
    __syncthreads();
    for (int idx = t; idx < NB * NB; idx += 256) {
        int r = idx >> 5, c = idx & 31;
        Pi[r][c] = d_Lfac[(size_t)(ri + r) * Nn + o + c];
        Pj[r][c] = d_Lfac[(size_t)(rj + r) * Nn + o + c];
    }
    __syncthreads();
    int ty = t >> 4, tx = t & 15;
    float acc[2][2] = {};
#pragma unroll 8
    for (int m = 0; m < NB; m++) {
        float ar[2], br[2];
#pragma unroll
        for (int i = 0; i < 2; i++) { ar[i] = Pi[ty * 2 + i][m]; br[i] = Pj[tx * 2 + i][m]; }
#pragma unroll
        for (int i = 0; i < 2; i++)
#pragma unroll
            for (int j = 0; j < 2; j++) acc[i][j] += ar[i] * br[j];
    }
    __syncthreads();
#pragma unroll
    for (int i = 0; i < 2; i++)
#pragma unroll
        for (int j = 0; j < 2; j++) {
            size_t idx = (size_t)(ri + ty * 2 + i) * Nn + rj + tx * 2 + j;
            d_S[idx] -= acc[i][j];
        }
    __syncthreads();
}

// forward + backward triangular solves by ONE block (256 threads), NB=32
__device__ void solve_dev(float* sh, float* shB) {
    int t = threadIdx.x;
    int r = t >> 3, q = t & 7;          // 32 rows x 8 threads
    float* yv   = sh;                   // 1024
    float* zz   = sh + 1024;            // 1024
    float* part = sh + 2048;            // 32
    float* tvv  = sh + 2080;            // 32
    for (int k = 0; k < NKB; k++) {
        int o = k * NB;
        float acc = 0.f;
        const float* Srow = &d_Lfac[(size_t)(o + r) * Nn + q * 4];
        for (int cb = 0; cb < k; cb++) {
            float4 v = *(const float4*)&Srow[cb * NB];
            int j = cb * NB + q * 4;
            acc += v.x * yv[j] + v.y * yv[j + 1] + v.z * yv[j + 2] + v.w * yv[j + 3];
        }
        acc += __shfl_xor_sync(0xffffffffu, acc, 1);
        acc += __shfl_xor_sync(0xffffffffu, acc, 2);
        acc += __shfl_xor_sync(0xffffffffu, acc, 4);
        if (q == 0) part[r] = acc;
        for (int idx = t; idx < NB * NB; idx += 256)
            shB[idx] = d_Linv[k * NB * NB + idx];
        __syncthreads();
        if (t < NB) tvv[t] = d_r[o + t] - part[t];
        __syncthreads();
        if (t < NB) {
            float a2 = 0.f;
#pragma unroll
            for (int m = 0; m < NB; m++) a2 += shB[t * NB + m] * tvv[m];
            yv[o + t] = a2;
        }
        __syncthreads();
    }
    for (int k = NKB - 1; k >= 0; k--) {
        int o = k * NB;
        float acc = 0.f;
        const float* Urow = &d_U[(size_t)(o + r) * Nn + q * 4];
        for (int rb = k + 1; rb < NKB; rb++) {
            float4 v = *(const float4*)&Urow[rb * NB];
            int j = rb * NB + q * 4;
            acc += v.x * zz[j] + v.y * zz[j + 1] + v.z * zz[j + 2] + v.w * zz[j + 3];
        }
        acc += __shfl_xor_sync(0xffffffffu, acc, 1);
        acc += __shfl_xor_sync(0xffffffffu, acc, 2);
        acc += __shfl_xor_sync(0xffffffffu, acc, 4);
        if (q == 0) part[r] = acc;
        for (int idx = t; idx < NB * NB; idx += 256)
            shB[idx] = d_Linv[k * NB * NB + idx];
        __syncthreads();
        if (t < NB) tvv[t] = yv[o + t] - part[t];
        __syncthreads();
        if (t < NB) {
            float a2 = 0.f;
#pragma unroll
            for (int m = 0; m < NB; m++) a2 += shB[m * NB + t] * tvv[m];
            zz[o + t] = a2;
        }
        __syncthreads();
    }
    for (int n = t; n < Nn; n += 256) d_z[n] = zz[n];
    __syncthreads();
}

__device__ void matvec_dev(const float* src, float* dst, int bid, int t, float* ws) {
    for (int row = bid; row < Nn; row += GPB) {
        float4 lv = *(const float4*)&d_L[(size_t)row * Nn + t * 4];
        float4 zv = *(const float4*)&src[t * 4];
        float acc = lv.x * zv.x + lv.y * zv.y + lv.z * zv.z + lv.w * zv.w;
        for (int off = 16; off; off >>= 1) acc += __shfl_down_sync(0xffffffffu, acc, off);
        if ((t & 31) == 0) ws[t >> 5] = acc;
        __syncthreads();
        if (t == 0) {
            float s = 0.f;
#pragma unroll
            for (int w = 0; w < 8; w++) s += ws[w];
            dst[row] = s;
        }
        __syncthreads();
    }
}

__global__ void __launch_bounds__(256, 1)
k_chol_all(const float* __restrict__ a, const float* __restrict__ y, float* __restrict__ out) {
    __shared__ float shAf[NB * (NB + 1)];
    __shared__ float shBf[NB * (NB + 1)];
    __shared__ float shS[2112];
    __shared__ float ws[8];
    int bid = blockIdx.x, t = threadIdx.x;
    float (*shA)[NB + 1] = (float (*)[NB + 1])shAf;
    float (*shB)[NB + 1] = (float (*)[NB + 1])shBf;

    // phase 0: potrf(0) on block 0; residual r on last block
    if (bid == 0) {
        potrf_from_global(0, shA, shB);
        setflag(&f_q, 1);
    } else if (bid == GPB - 1) {
        if (t == 0) { g_gen_dev[0] = 0u; g_cnt_dev[0] = 0u; }   // reset front barrier
        float a0 = a[0], a1 = a[1], a2 = a[2], a3 = a[3];
        for (int n = t; n < Nn; n += 256)
            d_r[n] = y[n] - (a0 * d_u[0][n] + a1 * d_u[1][n] + a2 * d_u[2][n] + a3 * d_u[3][n]);
        setflag(&f_res, 1);
    }

    for (int k = 0; k < NKB - 1; k++) {
        int rb = NKB - 1 - k;
        if (bid == 0) {
            // lookahead chain: private trsm(panel0) -> syrk(0,0) -> potrf(k+1)
            if (t == 0) { spin_ge(&f_t[(k + 1) * NKB + k], k); __threadfence(); }
            __syncthreads();
            trsm_dev(k, 0, shA, shB, false);           // P0 left in shA (row-major)
            if (t == 0) { spin_ge(&f_t[(k + 1) * NKB + (k + 1)], k); __threadfence(); }
            __syncthreads();
            {
                int ty = t >> 4, tx = t & 15;
                float acc[2][2] = {};
#pragma unroll 8
                for (int m = 0; m < NB; m++) {
                    float ar[2], br[2];
#pragma unroll
                    for (int i = 0; i < 2; i++) { ar[i] = shA[ty * 2 + i][m]; br[i] = shA[tx * 2 + i][m]; }
#pragma unroll
                    for (int i = 0; i < 2; i++)
#pragma unroll
                        for (int j = 0; j < 2; j++) acc[i][j] += ar[i] * br[j];
                }
                __syncthreads();
                int o2 = (k + 1) * NB;
#pragma unroll
                for (int i = 0; i < 2; i++)
#pragma unroll
                    for (int j = 0; j < 2; j++)
                        shB[ty * 2 + i][tx * 2 + j] =
                            d_S[(size_t)(o2 + ty * 2 + i) * Nn + o2 + tx * 2 + j] - acc[i][j];
                __syncthreads();
                for (int idx = t; idx < NB * NB; idx += 256) {
                    int r = idx >> 5, c = idx & 31;
                    shA[r][c] = (r == c) ? 1.f : 0.f;
                }
                potrf_core(k + 1, shB, shA);
            }
            setflag(&f_q, k + 2);
        } else {
            if (bid <= rb) {
                int I = k + bid;
                if (t == 0) {
                    spin_ge(&f_q, k + 1);
                    spin_ge(&f_t[I * NKB + k], k);
                    __threadfence();
                }
                __syncthreads();
                trsm_dev(k, bid - 1, shA, shB, true);
                setflag(&f_p[I], k + 1);
            }
            int T = rb * (rb + 1) / 2;
            for (int tt = bid; tt < T; tt += GPB - 1) {
                int bi = (int)((sqrtf(8.f * tt + 1.f) - 1.f) * 0.5f);
                while ((bi + 1) * (bi + 2) / 2 <= tt) bi++;
                while (bi * (bi + 1) / 2 > tt) bi--;
                int bj = tt - bi * (bi + 1) / 2;
                int I = k + 1 + bi, J = k + 1 + bj;
                if (t == 0) {
                    spin_ge(&f_p[I], k + 1);
                    spin_ge(&f_p[J], k + 1);
                    spin_ge(&f_t[I * NKB + J], k);
                    __threadfence();
                }
                __syncthreads();
                syrk_dev(k, bi, bj, shA, shB);
                setflag(&f_t[I * NKB + J], k + 1);
            }
        }
    }

    if (bid == 0) {
        if (t == 0) {
            for (int rb2 = 1; rb2 < NKB; rb2++) spin_ge(&f_p[rb2], rb2);
            spin_ge(&f_res, 1);
            __threadfence();
        }
        __syncthreads();
        solve_dev(shS, shBf);
        setflag(&f_z, 1);
    }
    if (t == 0) { spin_ge(&f_z, 1); __threadfence(); }
    __syncthreads();

    matvec_dev(d_z,  d_v1, bid, t, ws);
    gridbar(1, 1, GPB);
    matvec_dev(d_v1, d_v2, bid, t, ws);
    gridbar(1, 2, GPB);

    float a1 = a[1], a2 = a[2], a3 = a[3];
    for (int e = bid * 256 + t; e < Ee; e += GPB * 256) {
        int h = d_heads[e], tl = d_tails[e];
        float V0 = d_u[0][h] - d_u[0][tl];
        float V1 = d_u[1][h] - d_u[1][tl];
        float V2 = d_u[2][h] - d_u[2][tl];
        float w0 = a1 * V0 + a2 * V1 + a3 * V2;
        float w1 = a2 * V0 + a3 * V1;
        float w2 = a3 * V0;
        float dotv = w0 * (d_z[h] - d_z[tl]) + w1 * (d_v1[h] - d_v1[tl]) + w2 * (d_v2[h] - d_v2[tl]);
        out[e] = fmaxf(d_s[e] + d_sigma[e] * dotv, 0.f);
    }
}

// ---------------- launch ----------------
extern "C" void kernel_launch(void* const* d_in, const int* in_sizes, int n_in,
                              void* d_out, int out_size) {
    (void)in_sizes; (void)n_in; (void)out_size;
    const float* F  = (const float*)d_in[0];
    const float* B  = (const float*)d_in[1];
    const float* Cu = (const float*)d_in[2];
    const float* Cw = (const float*)d_in[3];
    const float* Cx = (const float*)d_in[4];
    const float* s0 = (const float*)d_in[5];
    const float* a  = (const float*)d_in[6];
    const float* q  = (const float*)d_in[7];
    const float* y  = (const float*)d_in[8];
    float* out = (float*)d_out;

    k_front<<<GPB, 256>>>(B, F, Cu, Cx, s0, q);     // #1
    k_gemmL2<<<dim3(16, 16), 256>>>();              // #2
    k_HtS<<<GPB, 256>>>(a, Cw);                     // #3
    k_chol_all<<<GPB, 256>>>(a, y, out);            // #4
}